// round 12
// baseline (speedup 1.0000x reference)
#include <cuda_runtime.h>
#include <math.h>

#define HW   96
#define NB   4
#define NT0  4
#define NT1  8
#define ZT   32
#define CIN  128          // NT0*ZT
#define TW   4
#define TH   2
#define PIXW (TW+4)       // 8
#define PIXH (TH+4)       // 6
#define NPIX (PIXW*PIXH)  // 48
#define PSTRIDE 140       // per-pixel smem stride in floats (4 groups of 32 + 4 pad each)
#define NTHR 256
// transpose scratch: per warp 640 floats at s_in[2120 + warp*640]; s_out uses [0,2120)
#define SCR_BASE 2120
#define SCR_WSTR 640
#define S_IN_SZ  7296     // >= 2120 + 8*640 + 16  (also >= NPIX*PSTRIDE = 6720)

// transposed input scratch: [n][h][w][c], c = i*32 + z
__device__ float g_xt[NB*HW*HW*CIN];

// ---------------- Kernel A: (N,T0,Z,H,W) -> (N,H,W,C) transpose ----------------
__global__ __launch_bounds__(256) void k_transpose(const float* __restrict__ in)
{
    __shared__ float tile[32][33];
    int wt = blockIdx.x;          // 0..2  (w tile of 32)
    int h  = blockIdx.y;          // 0..95
    int ni = blockIdx.z;          // 0..15 = n*4+i
    int n = ni >> 2, i = ni & 3;
    int tx = threadIdx.x, ty = threadIdx.y;
    int w0 = wt * 32;
    #pragma unroll
    for (int k = 0; k < 4; k++) {
        int z = ty + 8*k;
        tile[z][tx] = in[(((n*NT0 + i)*ZT + z)*HW + h)*HW + w0 + tx];
    }
    __syncthreads();
    #pragma unroll
    for (int k = 0; k < 4; k++) {
        int w = w0 + ty + 8*k;
        g_xt[((n*HW + h)*HW + w)*CIN + i*32 + tx] = tile[tx][ty + 8*k];
    }
}

// ---------------- packed f32x2 helpers ----------------
__device__ __forceinline__ unsigned long long pack2(float x, float y) {
    unsigned long long r;
    asm("mov.b64 %0, {%1,%2};" : "=l"(r) : "f"(x), "f"(y));
    return r;
}
__device__ __forceinline__ void fma2(unsigned long long& d, unsigned long long a, unsigned long long b) {
    asm("fma.rn.f32x2 %0, %1, %2, %3;" : "=l"(d) : "l"(a), "l"(b), "l"(d));
}

// ---------------- Kernel B: fused conv + capsule transform + routing ----------------
__global__ __launch_bounds__(NTHR, 3) void k_caps(
    const float* __restrict__ Wc,   // (T0,5,5,1,T1) = 800
    const float* __restrict__ Wp,   // (T0,16,T1)    = 512
    const float* __restrict__ Wa,   // (T0,16,T1)    = 512
    const float* __restrict__ Ba,   // (T0,T1)       = 32
    float* __restrict__ out)        // (N,8,32,H,W)
{
    __shared__ __align__(16) float s_in[S_IN_SZ];   // input tile / transpose scratch / s_out
    __shared__ __align__(16) float s_wc8[800];      // straight copy of Wc: [o][k][t1]
    __shared__ float s_mp[32*17];         // [o*8+T][r*4+c] normalized W_pos
    __shared__ float s_ma[32*17];         // [o*8+T][r*4+c] W_app
    __shared__ float s_ba[32];            // [o*8+T]

    const int tid = threadIdx.x;
    const int n  = blockIdx.z;
    const int h0 = blockIdx.y * TH;
    const int w0 = blockIdx.x * TW;

    // ---- stage params ----
    // m[T][r][c] = Wp[i*128 + T*16 + r*4 + c].
    #pragma unroll
    for (int k = 0; k < 2; k++) {
        int idx = tid + NTHR*k;
        int i = idx >> 7, T = (idx >> 4) & 7, rc = idx & 15;
        s_mp[(i*8 + T)*17 + rc] = Wp[idx];
        s_ma[(i*8 + T)*17 + rc] = Wa[idx];
    }
    #pragma unroll
    for (int k = 0; k < 4; k++) {
        int idx = tid + NTHR*k;
        if (idx < 800) s_wc8[idx] = Wc[idx];
    }
    if (tid < 32)  s_ba[tid] = Ba[tid];

    // ---- stage input tile (halo 2, zero pad OOB), float4 ----
    #pragma unroll
    for (int k = 0; k < 6; k++) {
        int L = tid + NTHR*k;           // 48*32 = 1536 float4 total
        int pix = L >> 5, c4 = L & 31;
        int c = c4 << 2;
        int py = pix >> 3, px = pix & 7;
        int gh = h0 - 2 + py, gw = w0 - 2 + px;
        float4 v = make_float4(0.f, 0.f, 0.f, 0.f);
        if (gh >= 0 && gh < HW && gw >= 0 && gw < HW)
            v = *reinterpret_cast<const float4*>(&g_xt[((n*HW + gh)*HW + gw)*CIN + c]);
        *reinterpret_cast<float4*>(&s_in[pix*PSTRIDE + c + ((c >> 5) << 2)]) = v;
    }
    __syncthreads();

    // ---- normalize W_pos columns: per (i,T,col): m /= sqrt(max(sum_r m^2,1e-12)) ----
    if (tid < 128) {
        int i = tid >> 5, T = (tid >> 2) & 7, cc = tid & 3;
        int base = (i*8 + T)*17;
        float s = 0.f;
        #pragma unroll
        for (int r = 0; r < 4; r++) { float v = s_mp[base + r*4 + cc]; s += v*v; }
        float inv = 1.f / sqrtf(fmaxf(s, 1e-12f));
        #pragma unroll
        for (int r = 0; r < 4; r++) s_mp[base + r*4 + cc] *= inv;
    }
    __syncthreads();

    // ---- lane roles ----
    const int warp = tid >> 5, lane = tid & 31;
    const int py = warp >> 2, px = warp & 3;       // pixel in 4x2 tile
    const int o  = lane >> 3;
    // conv role: lane = o*8 + zl*4 + a  -> owns 4 z channels, all 8 t1
    const int zl = (lane >> 2) & 1, a = lane & 3;
    const int zoff = (zl << 4) + (a << 2);         // z within o's 32 channels
    // epilogue role: lane = o*8 + T
    const int T = lane & 7;
    const int ta = T >> 1, zlr = T & 1;

    // ---- conv: acc[t1][j2] f32x2 over z-pairs; each lane loads distinct 16B/tap ----
    __align__(16) unsigned long long acc[8][2];
    #pragma unroll
    for (int t = 0; t < 8; t++) { acc[t][0] = 0ull; acc[t][1] = 0ull; }

    const float* pin_base = s_in + o*36 + zoff;
    const float4* wrow = reinterpret_cast<const float4*>(s_wc8 + o*200);
    #pragma unroll
    for (int ky = 0; ky < 5; ky++) {
        #pragma unroll
        for (int kx = 0; kx < 5; kx++) {
            int k = ky*5 + kx;
            float4 w03 = wrow[2*k];
            float4 w47 = wrow[2*k + 1];
            ulonglong2 x2 = *reinterpret_cast<const ulonglong2*>(
                pin_base + ((py + ky)*PIXW + (px + kx))*PSTRIDE);
            unsigned long long s;
            s = pack2(w03.x, w03.x); fma2(acc[0][0], x2.x, s); fma2(acc[0][1], x2.y, s);
            s = pack2(w03.y, w03.y); fma2(acc[1][0], x2.x, s); fma2(acc[1][1], x2.y, s);
            s = pack2(w03.z, w03.z); fma2(acc[2][0], x2.x, s); fma2(acc[2][1], x2.y, s);
            s = pack2(w03.w, w03.w); fma2(acc[3][0], x2.x, s); fma2(acc[3][1], x2.y, s);
            s = pack2(w47.x, w47.x); fma2(acc[4][0], x2.x, s); fma2(acc[4][1], x2.y, s);
            s = pack2(w47.y, w47.y); fma2(acc[5][0], x2.x, s); fma2(acc[5][1], x2.y, s);
            s = pack2(w47.z, w47.z); fma2(acc[6][0], x2.x, s); fma2(acc[6][1], x2.y, s);
            s = pack2(w47.w, w47.w); fma2(acc[7][0], x2.x, s); fma2(acc[7][1], x2.y, s);
        }
    }

    __syncthreads();   // all warps done reading s_in pixel data; scratch may be written

    // ---- in-warp 4x4 transpose via smem: (o,zl,a; 8 t1 x 4z) -> (o,T; 16z pos + 16z app)
    float* scr = s_in + SCR_BASE + warp*SCR_WSTR;  // 640 floats, rows of 40 (16 rows)
    float up[16], ua[16];
    // pass 1: pos (t1 0..3)
    #pragma unroll
    for (int t = 0; t < 4; t++)
        *reinterpret_cast<float4*>(&scr[(o*4 + t)*40 + zoff]) =
            *reinterpret_cast<const float4*>(&acc[t][0]);
    __syncwarp();
    #pragma unroll
    for (int g = 0; g < 4; g++) {
        float4 v = *reinterpret_cast<const float4*>(&scr[(o*4 + ta)*40 + zlr*16 + g*4]);
        up[g*4+0] = v.x; up[g*4+1] = v.y; up[g*4+2] = v.z; up[g*4+3] = v.w;
    }
    __syncwarp();
    // pass 2: app (t1 4..7)
    #pragma unroll
    for (int t = 0; t < 4; t++)
        *reinterpret_cast<float4*>(&scr[(o*4 + t)*40 + zoff]) =
            *reinterpret_cast<const float4*>(&acc[4 + t][0]);
    __syncwarp();
    #pragma unroll
    for (int g = 0; g < 4; g++) {
        float4 v = *reinterpret_cast<const float4*>(&scr[(o*4 + ta)*40 + zlr*16 + g*4]);
        ua[g*4+0] = v.x; ua[g*4+1] = v.y; ua[g*4+2] = v.z; ua[g*4+3] = v.w;
    }

    // ---- capsule transform: u_hat[z] ----
    float u[32];
    {
        float mm[16];
        #pragma unroll
        for (int q = 0; q < 16; q++) mm[q] = s_mp[lane*17 + q];
        mm[12] += (float)(w0 + px) * (1.f/96.f);   // coord add: M[3][0] += x/W
        mm[13] += (float)(h0 + py) * (1.f/96.f);   //            M[3][1] += y/H
        #pragma unroll
        for (int aa = 0; aa < 4; aa++) {
            float r0 = up[4*aa+0], r1 = up[4*aa+1], r2 = up[4*aa+2], r3 = up[4*aa+3];
            #pragma unroll
            for (int b = 0; b < 4; b++)
                u[aa*4+b] = r0*mm[b] + r1*mm[4+b] + r2*mm[8+b] + r3*mm[12+b];
        }
        float bap = s_ba[lane];
        #pragma unroll
        for (int q = 0; q < 16; q++) mm[q] = s_ma[lane*17 + q];
        #pragma unroll
        for (int aa = 0; aa < 4; aa++) {
            float r0 = ua[4*aa+0]+bap, r1 = ua[4*aa+1]+bap, r2 = ua[4*aa+2]+bap, r3 = ua[4*aa+3]+bap;
            #pragma unroll
            for (int b = 0; b < 4; b++)
                u[16 + aa*4 + b] = r0*mm[b] + r1*mm[4+b] + r2*mm[8+b] + r3*mm[12+b];
        }
    }

    float* s_out = s_in;                // output stage [pix*265 + T*33 + z], region [0,2120)

    // ---- dynamic routing (3 passes; last writes v) ----
    float blog = 0.f;
    #pragma unroll
    for (int it = 0; it < 3; it++) {
        float r = 1.f / (1.f + __expf(-blog));
        float p[32];
        #pragma unroll
        for (int z = 0; z < 32; z++) {
            float v = u[z] * r;
            v += __shfl_xor_sync(0xffffffffu, v, 8);
            v += __shfl_xor_sync(0xffffffffu, v, 16);
            p[z] = v;                   // p[T][z], identical across o-lanes of same T
        }
        float mx = fabsf(p[0]);
        #pragma unroll
        for (int z = 1; z < 16; z++) mx = fmaxf(mx, fabsf(p[z]));
        float n2 = 0.f;
        #pragma unroll
        for (int z = 16; z < 32; z++) n2 = fmaf(p[z], p[z], n2);
        float sp = 1.f / mx;                                  // psquash scale
        float nn = sqrtf(n2 + 1e-9f);
        float sa = n2 / ((1.f + n2) * nn);                    // matwo squash scale
        if (it < 2) {
            float dp = 0.f, da = 0.f;
            #pragma unroll
            for (int z = 0;  z < 16; z++) dp = fmaf(u[z], p[z], dp);
            #pragma unroll
            for (int z = 16; z < 32; z++) da = fmaf(u[z], p[z], da);
            blog += (dp * sp) * (da * sa);
        } else if (o == 0) {
            #pragma unroll
            for (int z = 0; z < 32; z++)
                s_out[warp*265 + T*33 + z] = p[z] * (z < 16 ? sp : sa);
        }
    }
    __syncthreads();

    // ---- output write: out[n][t][z][h][w] (16B runs of w) ----
    #pragma unroll
    for (int k = 0; k < 8; k++) {
        int e = tid + k*NTHR;           // 8 pixels x 256 (t,z)
        int pix = e & 7, tz = e >> 3;
        int t = tz >> 5, z = tz & 31;
        int gh = h0 + (pix >> 2), gw = w0 + (pix & 3);
        out[(((n*8 + t)*32 + z)*HW + gh)*HW + gw] = s_out[pix*265 + t*33 + z];
    }
}

extern "C" void kernel_launch(void* const* d_in, const int* in_sizes, int n_in,
                              void* d_out, int out_size)
{
    (void)in_sizes; (void)n_in; (void)out_size;
    const float* x  = (const float*)d_in[0];
    const float* Wc = (const float*)d_in[1];
    const float* Wp = (const float*)d_in[2];
    const float* Wa = (const float*)d_in[3];
    const float* Ba = (const float*)d_in[4];
    float* out = (float*)d_out;

    dim3 gA(3, 96, 16), bA(32, 8);
    k_transpose<<<gA, bA>>>(x);

    dim3 gB(HW/TW, HW/TH, NB);          // (24, 48, 4)
    k_caps<<<gB, NTHR>>>(Wc, Wp, Wa, Ba, out);
}

// round 13
// speedup vs baseline: 2.0712x; 2.0712x over previous
#include <cuda_runtime.h>
#include <math.h>

#define HW   96
#define NB   4
#define NT0  4
#define NT1  8
#define ZT   32
#define CIN  128          // NT0*ZT
#define TW   4
#define TH   2
#define PIXW (TW+4)       // 8
#define PIXH (TH+4)       // 6
#define NPIX (PIXW*PIXH)  // 48
#define PSTRIDE 140       // per-pixel smem stride in floats (4 groups of 32 + 4 pad each)
#define NTHR 256
// s_out layout: [pix*292 + T*36 + z]  (16B-aligned slices, conflict-free)
#define OPIX 292
#define OT   36

// transposed input scratch: [n][h][w][c], c = i*32 + z
__device__ float g_xt[NB*HW*HW*CIN];

// ---------------- Kernel A: (N,T0,Z,H,W) -> (N,H,W,C) transpose ----------------
__global__ __launch_bounds__(256) void k_transpose(const float* __restrict__ in)
{
    __shared__ float tile[32][33];
    int wt = blockIdx.x;          // 0..2  (w tile of 32)
    int h  = blockIdx.y;          // 0..95
    int ni = blockIdx.z;          // 0..15 = n*4+i
    int n = ni >> 2, i = ni & 3;
    int tx = threadIdx.x, ty = threadIdx.y;
    int w0 = wt * 32;
    #pragma unroll
    for (int k = 0; k < 4; k++) {
        int z = ty + 8*k;
        tile[z][tx] = in[(((n*NT0 + i)*ZT + z)*HW + h)*HW + w0 + tx];
    }
    __syncthreads();
    #pragma unroll
    for (int k = 0; k < 4; k++) {
        int w = w0 + ty + 8*k;
        g_xt[((n*HW + h)*HW + w)*CIN + i*32 + tx] = tile[tx][ty + 8*k];
    }
}

// ---------------- packed f32x2 helpers ----------------
__device__ __forceinline__ unsigned long long pack2(float x, float y) {
    unsigned long long r;
    asm("mov.b64 %0, {%1,%2};" : "=l"(r) : "f"(x), "f"(y));
    return r;
}
__device__ __forceinline__ void fma2(unsigned long long& d, unsigned long long a, unsigned long long b) {
    asm("fma.rn.f32x2 %0, %1, %2, %3;" : "=l"(d) : "l"(a), "l"(b), "l"(d));
}
__device__ __forceinline__ void unpack2(unsigned long long v, float& lo, float& hi) {
    asm("mov.b64 {%0,%1}, %2;" : "=f"(lo), "=f"(hi) : "l"(v));
}

// ---------------- Kernel B: fused conv + capsule transform + routing ----------------
__global__ __launch_bounds__(NTHR, 3) void k_caps(
    const float* __restrict__ Wc,   // (T0,5,5,1,T1) = 800
    const float* __restrict__ Wp,   // (T0,16,T1)    = 512
    const float* __restrict__ Wa,   // (T0,16,T1)    = 512
    const float* __restrict__ Ba,   // (T0,T1)       = 32
    float* __restrict__ out)        // (N,8,32,H,W)
{
    __shared__ __align__(16) float s_in[NPIX*PSTRIDE]; // 6720 floats; reused as s_out
    __shared__ float2 s_wcp[400];         // [(o*4+ta)*25 + k] = (Wc[o,k,ta], Wc[o,k,ta+4])
    __shared__ float s_mp[32*17];         // [o*8+T][r*4+c] normalized W_pos
    __shared__ float s_ma[32*17];         // [o*8+T][r*4+c] W_app
    __shared__ float s_ba[32];            // [o*8+T]

    const int tid = threadIdx.x;
    const int n  = blockIdx.z;
    const int h0 = blockIdx.y * TH;
    const int w0 = blockIdx.x * TW;

    // ---- stage params ----  m[T][r][c] = Wp[i*128 + T*16 + r*4 + c]
    #pragma unroll
    for (int k = 0; k < 2; k++) {
        int idx = tid + NTHR*k;
        int i = idx >> 7, T = (idx >> 4) & 7, rc = idx & 15;
        s_mp[(i*8 + T)*17 + rc] = Wp[idx];
        s_ma[(i*8 + T)*17 + rc] = Wa[idx];
    }
    #pragma unroll
    for (int k = 0; k < 2; k++) {
        int idx = tid + NTHR*k;
        if (idx < 400) {
            int o = idx / 100, rem = idx - o*100;
            int ta = rem / 25, kk = rem - ta*25;
            s_wcp[idx] = make_float2(Wc[o*200 + kk*8 + ta], Wc[o*200 + kk*8 + ta + 4]);
        }
    }
    if (tid < 32)  s_ba[tid] = Ba[tid];

    // ---- stage input tile (halo 2, zero pad OOB), float4 ----
    #pragma unroll
    for (int k = 0; k < 6; k++) {
        int L = tid + NTHR*k;           // 48*32 = 1536 float4 total
        int pix = L >> 5, c4 = L & 31;
        int c = c4 << 2;
        int py = pix >> 3, px = pix & 7;
        int gh = h0 - 2 + py, gw = w0 - 2 + px;
        float4 v = make_float4(0.f, 0.f, 0.f, 0.f);
        if (gh >= 0 && gh < HW && gw >= 0 && gw < HW)
            v = *reinterpret_cast<const float4*>(&g_xt[((n*HW + gh)*HW + gw)*CIN + c]);
        *reinterpret_cast<float4*>(&s_in[pix*PSTRIDE + c + ((c >> 5) << 2)]) = v;
    }
    __syncthreads();

    // ---- normalize W_pos columns ----
    if (tid < 128) {
        int i = tid >> 5, T = (tid >> 2) & 7, cc = tid & 3;
        int base = (i*8 + T)*17;
        float s = 0.f;
        #pragma unroll
        for (int r = 0; r < 4; r++) { float v = s_mp[base + r*4 + cc]; s += v*v; }
        float inv = 1.f / sqrtf(fmaxf(s, 1e-12f));
        #pragma unroll
        for (int r = 0; r < 4; r++) s_mp[base + r*4 + cc] *= inv;
    }
    __syncthreads();

    // ---- per-warp pixel, per-lane (o,T) ----
    const int warp = tid >> 5, lane = tid & 31;
    const int py = warp >> 2, px = warp & 3;       // pixel in 4x2 tile
    const int o = lane >> 3,  T = lane & 7;
    const int ta = T >> 1;                          // conv t1 (pos); app half = ta+4
    const int zlo = (T & 1) << 4;
    const int wbase = (o*4 + ta)*25;

    // conv (R10 layout): aP/aA f32x2 accumulators
    unsigned long long aP[8], aA[8];
    #pragma unroll
    for (int j = 0; j < 8; j++) { aP[j] = 0ull; aA[j] = 0ull; }

    #pragma unroll
    for (int ky = 0; ky < 5; ky++) {
        #pragma unroll
        for (int kx = 0; kx < 5; kx++) {
            int k = ky*5 + kx;
            float2 wab = s_wcp[wbase + k];
            unsigned long long wa2 = pack2(wab.x, wab.x);
            unsigned long long wb2 = pack2(wab.y, wab.y);
            const ulonglong2* pin = reinterpret_cast<const ulonglong2*>(
                s_in + ((py + ky)*PIXW + (px + kx))*PSTRIDE + o*36 + zlo);
            #pragma unroll
            for (int jj = 0; jj < 4; jj++) {
                ulonglong2 x2 = pin[jj];
                fma2(aP[2*jj],   x2.x, wa2);
                fma2(aP[2*jj+1], x2.y, wa2);
                fma2(aA[2*jj],   x2.x, wb2);
                fma2(aA[2*jj+1], x2.y, wb2);
            }
        }
    }

    float up[16], ua[16];
    #pragma unroll
    for (int j = 0; j < 8; j++) {
        unpack2(aP[j], up[2*j], up[2*j+1]);
        unpack2(aA[j], ua[2*j], ua[2*j+1]);
    }

    // ---- capsule transform: u_hat[z], column layout (own o, all 32 z) ----
    float u[32];
    {
        float mm[16];
        #pragma unroll
        for (int q = 0; q < 16; q++) mm[q] = s_mp[lane*17 + q];
        mm[12] += (float)(w0 + px) * (1.f/96.f);
        mm[13] += (float)(h0 + py) * (1.f/96.f);
        #pragma unroll
        for (int a = 0; a < 4; a++) {
            float r0 = up[4*a+0], r1 = up[4*a+1], r2 = up[4*a+2], r3 = up[4*a+3];
            #pragma unroll
            for (int b = 0; b < 4; b++)
                u[a*4+b] = r0*mm[b] + r1*mm[4+b] + r2*mm[8+b] + r3*mm[12+b];
        }
        float bap = s_ba[lane];
        #pragma unroll
        for (int q = 0; q < 16; q++) mm[q] = s_ma[lane*17 + q];
        #pragma unroll
        for (int a = 0; a < 4; a++) {
            float r0 = ua[4*a+0]+bap, r1 = ua[4*a+1]+bap, r2 = ua[4*a+2]+bap, r3 = ua[4*a+3]+bap;
            #pragma unroll
            for (int b = 0; b < 4; b++)
                u[16 + a*4 + b] = r0*mm[b] + r1*mm[4+b] + r2*mm[8+b] + r3*mm[12+b];
        }
    }

    // ---- one-time warp transpose: columns -> slices ----
    // after: v_j[k] = u_{o^j}[o*8 + k],  k=0..7  (slot j = column ^ o)
    float keepv[16], othv[16];
    {
        const bool lowh = (o < 2);            // bit1(o)==0 -> keeps z[0,16)
        #pragma unroll
        for (int zz = 0; zz < 16; zz++) {
            float tosend = lowh ? u[16+zz] : u[zz];
            float got = __shfl_xor_sync(0xffffffffu, tosend, 16);
            keepv[zz] = lowh ? u[zz] : u[16+zz];   // own column, own half
            othv[zz]  = got;                        // column o^2, own half
        }
    }
    float v0[8], v1[8], v2[8], v3[8];
    {
        const bool lowq = ((o & 1) == 0);     // bit0(o)==0 -> keeps lower 8 of half
        #pragma unroll
        for (int k = 0; k < 8; k++) {
            float sA = lowq ? keepv[8+k] : keepv[k];
            float sB = lowq ? othv[8+k]  : othv[k];
            float g1 = __shfl_xor_sync(0xffffffffu, sA, 8);
            float g2 = __shfl_xor_sync(0xffffffffu, sB, 8);
            v0[k] = lowq ? keepv[k] : keepv[8+k];   // column o
            v2[k] = lowq ? othv[k]  : othv[8+k];    // column o^2
            v1[k] = g1;                             // column o^1
            v3[k] = g2;                             // column o^3
        }
    }

    float* s_out = s_in;   // [pix*OPIX + T*OT + z]; writes after per-warp conv reads done
                           // (each warp reads only its own pixel rows before writing;
                           //  cross-warp safety needs a barrier:)
    __syncthreads();

    // ---- dynamic routing: p local, few shfls ----
    const bool posl = (o < 2);
    float blog = 0.f, sp = 0.f, sa = 0.f;
    float pl[8];
    #pragma unroll
    for (int it = 0; it < 3; it++) {
        float r = 1.f / (1.f + __expf(-blog));
        float a0 = r;
        float a1 = __shfl_xor_sync(0xffffffffu, r, 8);
        float a2 = __shfl_xor_sync(0xffffffffu, r, 16);
        float a3 = __shfl_xor_sync(0xffffffffu, r, 24);
        #pragma unroll
        for (int k = 0; k < 8; k++)
            pl[k] = v0[k]*a0 + v1[k]*a1 + v2[k]*a2 + v3[k]*a3;
        // squash stats: pos lanes (o<2) own z<16 -> max|p|; app lanes own z>=16 -> sum p^2
        float mloc = fabsf(pl[0]);
        float nloc = pl[0]*pl[0];
        #pragma unroll
        for (int k = 1; k < 8; k++) {
            mloc = fmaxf(mloc, fabsf(pl[k]));
            nloc = fmaf(pl[k], pl[k], nloc);
        }
        float m2 = fmaxf(mloc, __shfl_xor_sync(0xffffffffu, mloc, 8));
        float s2 = nloc + __shfl_xor_sync(0xffffffffu, nloc, 8);
        float val = posl ? m2 : s2;
        float w_  = __shfl_xor_sync(0xffffffffu, val, 16);
        float mx = posl ? m2 : w_;
        float n2 = posl ? w_ : s2;
        sp = 1.f / mx;
        float nn = sqrtf(n2 + 1e-9f);
        sa = n2 / ((1.f + n2) * nn);
        if (it < 2) {
            float q0 = 0.f, q1 = 0.f, q2 = 0.f, q3 = 0.f;
            #pragma unroll
            for (int k = 0; k < 8; k++) {
                q0 = fmaf(v0[k], pl[k], q0);
                q1 = fmaf(v1[k], pl[k], q1);
                q2 = fmaf(v2[k], pl[k], q2);
                q3 = fmaf(v3[k], pl[k], q3);
            }
            float Q0 = q0 + __shfl_xor_sync(0xffffffffu, q1, 8);  // own col, own range
            float Q2 = q2 + __shfl_xor_sync(0xffffffffu, q3, 8);  // col o^2, own range
            float D0 = __shfl_xor_sync(0xffffffffu, Q2, 16);      // own col, other range
            float dp = posl ? Q0 : D0;
            float da = posl ? D0 : Q0;
            blog += (dp * sp) * (da * sa);
        }
    }
    // final v: scale and store 8 floats (z = o*8..o*8+7)
    {
        float scl = posl ? sp : sa;
        float4* dst = reinterpret_cast<float4*>(&s_out[warp*OPIX + T*OT + o*8]);
        dst[0] = make_float4(pl[0]*scl, pl[1]*scl, pl[2]*scl, pl[3]*scl);
        dst[1] = make_float4(pl[4]*scl, pl[5]*scl, pl[6]*scl, pl[7]*scl);
    }
    __syncthreads();

    // ---- output write: out[n][t][z][h][w] (16B runs of w) ----
    #pragma unroll
    for (int k = 0; k < 8; k++) {
        int e = tid + k*NTHR;           // 8 pixels x 256 (t,z)
        int pix = e & 7, tz = e >> 3;
        int t = tz >> 5, z = tz & 31;
        int gh = h0 + (pix >> 2), gw = w0 + (pix & 3);
        out[(((n*8 + t)*32 + z)*HW + gh)*HW + gw] = s_out[pix*OPIX + t*OT + z];
    }
}

extern "C" void kernel_launch(void* const* d_in, const int* in_sizes, int n_in,
                              void* d_out, int out_size)
{
    (void)in_sizes; (void)n_in; (void)out_size;
    const float* x  = (const float*)d_in[0];
    const float* Wc = (const float*)d_in[1];
    const float* Wp = (const float*)d_in[2];
    const float* Wa = (const float*)d_in[3];
    const float* Ba = (const float*)d_in[4];
    float* out = (float*)d_out;

    dim3 gA(3, 96, 16), bA(32, 8);
    k_transpose<<<gA, bA>>>(x);

    dim3 gB(HW/TW, HW/TH, NB);          // (24, 48, 4)
    k_caps<<<gB, NTHR>>>(Wc, Wp, Wa, Ba, out);
}

// round 14
// speedup vs baseline: 2.0720x; 1.0004x over previous
#include <cuda_runtime.h>
#include <math.h>

#define HW   96
#define NB   4
#define NT0  4
#define NT1  8
#define ZT   32
#define CIN  128          // NT0*ZT
#define TW   4
#define TH   4
#define PIXW (TW+4)       // 8
#define PIXH (TH+4)       // 8
#define NPIX (PIXW*PIXH)  // 64
#define PSTRIDE 140       // per-pixel smem stride in floats (4 groups of 32 + 4 pad each)
#define NTHR 256
// s_out layout: [pix*292 + T*36 + z]  (16B-aligned slices)
#define OPIX 292
#define OT   36

// transposed input scratch: [n][h][w][c], c = i*32 + z
__device__ float g_xt[NB*HW*HW*CIN];

// ---------------- Kernel A: (N,T0,Z,H,W) -> (N,H,W,C) transpose ----------------
__global__ __launch_bounds__(256) void k_transpose(const float* __restrict__ in)
{
    __shared__ float tile[32][33];
    int wt = blockIdx.x;          // 0..2  (w tile of 32)
    int h  = blockIdx.y;          // 0..95
    int ni = blockIdx.z;          // 0..15 = n*4+i
    int n = ni >> 2, i = ni & 3;
    int tx = threadIdx.x, ty = threadIdx.y;
    int w0 = wt * 32;
    #pragma unroll
    for (int k = 0; k < 4; k++) {
        int z = ty + 8*k;
        tile[z][tx] = in[(((n*NT0 + i)*ZT + z)*HW + h)*HW + w0 + tx];
    }
    __syncthreads();
    #pragma unroll
    for (int k = 0; k < 4; k++) {
        int w = w0 + ty + 8*k;
        g_xt[((n*HW + h)*HW + w)*CIN + i*32 + tx] = tile[tx][ty + 8*k];
    }
}

// ---------------- packed f32x2 helpers ----------------
__device__ __forceinline__ unsigned long long pack2(float x, float y) {
    unsigned long long r;
    asm("mov.b64 %0, {%1,%2};" : "=l"(r) : "f"(x), "f"(y));
    return r;
}
__device__ __forceinline__ void fma2(unsigned long long& d, unsigned long long a, unsigned long long b) {
    asm("fma.rn.f32x2 %0, %1, %2, %3;" : "=l"(d) : "l"(a), "l"(b), "l"(d));
}
__device__ __forceinline__ void unpack2(unsigned long long v, float& lo, float& hi) {
    asm("mov.b64 {%0,%1}, %2;" : "=f"(lo), "=f"(hi) : "l"(v));
}

// ---------------- Kernel B: fused conv + capsule transform + routing ----------------
__global__ __launch_bounds__(NTHR, 2) void k_caps(
    const float* __restrict__ Wc,   // (T0,5,5,1,T1) = 800
    const float* __restrict__ Wp,   // (T0,16,T1)    = 512
    const float* __restrict__ Wa,   // (T0,16,T1)    = 512
    const float* __restrict__ Ba,   // (T0,T1)       = 32
    float* __restrict__ out)        // (N,8,32,H,W)
{
    __shared__ __align__(16) float s_in[NPIX*PSTRIDE]; // 8960 floats; reused as s_out
    __shared__ float2 s_wcp[400];         // [(o*4+ta)*25 + k] = (Wc[o,k,ta], Wc[o,k,ta+4])
    __shared__ float s_mp[32*17];         // [o*8+T][r*4+c] normalized W_pos
    __shared__ float s_ma[32*17];         // [o*8+T][r*4+c] W_app
    __shared__ float s_ba[32];            // [o*8+T]

    const int tid = threadIdx.x;
    const int n  = blockIdx.z;
    const int h0 = blockIdx.y * TH;
    const int w0 = blockIdx.x * TW;

    // ---- stage params ----  m[T][r][c] = Wp[i*128 + T*16 + r*4 + c]
    #pragma unroll
    for (int k = 0; k < 2; k++) {
        int idx = tid + NTHR*k;
        int i = idx >> 7, T = (idx >> 4) & 7, rc = idx & 15;
        s_mp[(i*8 + T)*17 + rc] = Wp[idx];
        s_ma[(i*8 + T)*17 + rc] = Wa[idx];
    }
    #pragma unroll
    for (int k = 0; k < 2; k++) {
        int idx = tid + NTHR*k;
        if (idx < 400) {
            int o = idx / 100, rem = idx - o*100;
            int ta = rem / 25, kk = rem - ta*25;
            s_wcp[idx] = make_float2(Wc[o*200 + kk*8 + ta], Wc[o*200 + kk*8 + ta + 4]);
        }
    }
    if (tid < 32)  s_ba[tid] = Ba[tid];

    // ---- stage input tile (halo 2, zero pad OOB), float4 ----
    #pragma unroll
    for (int k = 0; k < 8; k++) {
        int L = tid + NTHR*k;           // 64*32 = 2048 float4 total
        int pix = L >> 5, c4 = L & 31;
        int c = c4 << 2;
        int py = pix >> 3, px = pix & 7;
        int gh = h0 - 2 + py, gw = w0 - 2 + px;
        float4 v = make_float4(0.f, 0.f, 0.f, 0.f);
        if (gh >= 0 && gh < HW && gw >= 0 && gw < HW)
            v = *reinterpret_cast<const float4*>(&g_xt[((n*HW + gh)*HW + gw)*CIN + c]);
        *reinterpret_cast<float4*>(&s_in[pix*PSTRIDE + c + ((c >> 5) << 2)]) = v;
    }
    __syncthreads();

    // ---- normalize W_pos columns ----
    if (tid < 128) {
        int i = tid >> 5, T = (tid >> 2) & 7, cc = tid & 3;
        int base = (i*8 + T)*17;
        float s = 0.f;
        #pragma unroll
        for (int r = 0; r < 4; r++) { float v = s_mp[base + r*4 + cc]; s += v*v; }
        float inv = 1.f / sqrtf(fmaxf(s, 1e-12f));
        #pragma unroll
        for (int r = 0; r < 4; r++) s_mp[base + r*4 + cc] *= inv;
    }
    __syncthreads();

    // ---- per-warp pixel column, 2 output rows per lane ----
    const int warp = tid >> 5, lane = tid & 31;
    const int wy = warp >> 2, px = warp & 3;       // px: pixel column in tile
    const int py0 = wy * 2;                        // first output row of this warp
    const int o = lane >> 3,  T = lane & 7;
    const int ta = T >> 1;                          // conv t1 (pos); app half = ta+4
    const int zlo = (T & 1) << 4;
    const int wbase = (o*4 + ta)*25;

    // conv accumulators for 2 rows, f32x2
    unsigned long long aP0[8], aA0[8], aP1[8], aA1[8];
    #pragma unroll
    for (int j = 0; j < 8; j++) { aP0[j]=0ull; aA0[j]=0ull; aP1[j]=0ull; aA1[j]=0ull; }

    // input rows py0..py0+5 loaded once; row0 uses weight row j, row1 uses j-1
    #pragma unroll
    for (int j = 0; j < 6; j++) {
        #pragma unroll
        for (int kx = 0; kx < 5; kx++) {
            const ulonglong2* pin = reinterpret_cast<const ulonglong2*>(
                s_in + ((py0 + j)*PIXW + (px + kx))*PSTRIDE + o*36 + zlo);
            ulonglong2 xA = pin[0];
            ulonglong2 xB = pin[1];
            ulonglong2 xC = pin[2];
            ulonglong2 xD = pin[3];
            if (j < 5) {
                float2 wab = s_wcp[wbase + j*5 + kx];
                unsigned long long wa2 = pack2(wab.x, wab.x);
                unsigned long long wb2 = pack2(wab.y, wab.y);
                fma2(aP0[0], xA.x, wa2); fma2(aP0[1], xA.y, wa2);
                fma2(aP0[2], xB.x, wa2); fma2(aP0[3], xB.y, wa2);
                fma2(aP0[4], xC.x, wa2); fma2(aP0[5], xC.y, wa2);
                fma2(aP0[6], xD.x, wa2); fma2(aP0[7], xD.y, wa2);
                fma2(aA0[0], xA.x, wb2); fma2(aA0[1], xA.y, wb2);
                fma2(aA0[2], xB.x, wb2); fma2(aA0[3], xB.y, wb2);
                fma2(aA0[4], xC.x, wb2); fma2(aA0[5], xC.y, wb2);
                fma2(aA0[6], xD.x, wb2); fma2(aA0[7], xD.y, wb2);
            }
            if (j > 0) {
                float2 wab = s_wcp[wbase + (j-1)*5 + kx];
                unsigned long long wa2 = pack2(wab.x, wab.x);
                unsigned long long wb2 = pack2(wab.y, wab.y);
                fma2(aP1[0], xA.x, wa2); fma2(aP1[1], xA.y, wa2);
                fma2(aP1[2], xB.x, wa2); fma2(aP1[3], xB.y, wa2);
                fma2(aP1[4], xC.x, wa2); fma2(aP1[5], xC.y, wa2);
                fma2(aP1[6], xD.x, wa2); fma2(aP1[7], xD.y, wa2);
                fma2(aA1[0], xA.x, wb2); fma2(aA1[1], xA.y, wb2);
                fma2(aA1[2], xB.x, wb2); fma2(aA1[3], xB.y, wb2);
                fma2(aA1[4], xC.x, wb2); fma2(aA1[5], xC.y, wb2);
                fma2(aA1[6], xD.x, wb2); fma2(aA1[7], xD.y, wb2);
            }
        }
    }

    __syncthreads();                // all warps done reading s_in tile data
    float* s_out = s_in;            // [pix16*OPIX + T*OT + z], region [0, 16*292)

    const bool posl = (o < 2);
    const bool lowh = (o < 2);      // bit1(o)==0 -> keeps z[0,16)
    const bool lowq = ((o & 1) == 0);

    #pragma unroll
    for (int rr = 0; rr < 2; rr++) {
        const int pyr = py0 + rr;

        float up[16], ua[16];
        #pragma unroll
        for (int j = 0; j < 8; j++) {
            unpack2(rr == 0 ? aP0[j] : aP1[j], up[2*j], up[2*j+1]);
            unpack2(rr == 0 ? aA0[j] : aA1[j], ua[2*j], ua[2*j+1]);
        }

        // ---- capsule transform: u_hat[z], column layout ----
        float u[32];
        {
            float mm[16];
            #pragma unroll
            for (int q = 0; q < 16; q++) mm[q] = s_mp[lane*17 + q];
            mm[12] += (float)(w0 + px) * (1.f/96.f);
            mm[13] += (float)(h0 + pyr) * (1.f/96.f);
            #pragma unroll
            for (int a = 0; a < 4; a++) {
                float r0 = up[4*a+0], r1 = up[4*a+1], r2 = up[4*a+2], r3 = up[4*a+3];
                #pragma unroll
                for (int b = 0; b < 4; b++)
                    u[a*4+b] = r0*mm[b] + r1*mm[4+b] + r2*mm[8+b] + r3*mm[12+b];
            }
            float bap = s_ba[lane];
            #pragma unroll
            for (int q = 0; q < 16; q++) mm[q] = s_ma[lane*17 + q];
            #pragma unroll
            for (int a = 0; a < 4; a++) {
                float r0 = ua[4*a+0]+bap, r1 = ua[4*a+1]+bap, r2 = ua[4*a+2]+bap, r3 = ua[4*a+3]+bap;
                #pragma unroll
                for (int b = 0; b < 4; b++)
                    u[16 + a*4 + b] = r0*mm[b] + r1*mm[4+b] + r2*mm[8+b] + r3*mm[12+b];
            }
        }

        // ---- one-time warp transpose: columns -> slices ----
        float keepv[16], othv[16];
        #pragma unroll
        for (int zz = 0; zz < 16; zz++) {
            float tosend = lowh ? u[16+zz] : u[zz];
            float got = __shfl_xor_sync(0xffffffffu, tosend, 16);
            keepv[zz] = lowh ? u[zz] : u[16+zz];
            othv[zz]  = got;
        }
        float v0[8], v1[8], v2[8], v3[8];
        #pragma unroll
        for (int k = 0; k < 8; k++) {
            float sA = lowq ? keepv[8+k] : keepv[k];
            float sB = lowq ? othv[8+k]  : othv[k];
            float g1 = __shfl_xor_sync(0xffffffffu, sA, 8);
            float g2 = __shfl_xor_sync(0xffffffffu, sB, 8);
            v0[k] = lowq ? keepv[k] : keepv[8+k];
            v2[k] = lowq ? othv[k]  : othv[8+k];
            v1[k] = g1;
            v3[k] = g2;
        }

        // ---- dynamic routing ----
        float blog = 0.f, sp = 0.f, sa = 0.f;
        float pl[8];
        #pragma unroll
        for (int it = 0; it < 3; it++) {
            float r = 1.f / (1.f + __expf(-blog));
            float a0 = r;
            float a1 = __shfl_xor_sync(0xffffffffu, r, 8);
            float a2 = __shfl_xor_sync(0xffffffffu, r, 16);
            float a3 = __shfl_xor_sync(0xffffffffu, r, 24);
            #pragma unroll
            for (int k = 0; k < 8; k++)
                pl[k] = v0[k]*a0 + v1[k]*a1 + v2[k]*a2 + v3[k]*a3;
            float mloc = fabsf(pl[0]);
            float nloc = pl[0]*pl[0];
            #pragma unroll
            for (int k = 1; k < 8; k++) {
                mloc = fmaxf(mloc, fabsf(pl[k]));
                nloc = fmaf(pl[k], pl[k], nloc);
            }
            float m2 = fmaxf(mloc, __shfl_xor_sync(0xffffffffu, mloc, 8));
            float s2 = nloc + __shfl_xor_sync(0xffffffffu, nloc, 8);
            float val = posl ? m2 : s2;
            float w_  = __shfl_xor_sync(0xffffffffu, val, 16);
            float mx = posl ? m2 : w_;
            float n2 = posl ? w_ : s2;
            sp = 1.f / mx;
            float nn = sqrtf(n2 + 1e-9f);
            sa = n2 / ((1.f + n2) * nn);
            if (it < 2) {
                float q0 = 0.f, q1 = 0.f, q2 = 0.f, q3 = 0.f;
                #pragma unroll
                for (int k = 0; k < 8; k++) {
                    q0 = fmaf(v0[k], pl[k], q0);
                    q1 = fmaf(v1[k], pl[k], q1);
                    q2 = fmaf(v2[k], pl[k], q2);
                    q3 = fmaf(v3[k], pl[k], q3);
                }
                float Q0 = q0 + __shfl_xor_sync(0xffffffffu, q1, 8);
                float Q2 = q2 + __shfl_xor_sync(0xffffffffu, q3, 8);
                float D0 = __shfl_xor_sync(0xffffffffu, Q2, 16);
                float dp = posl ? Q0 : D0;
                float da = posl ? D0 : Q0;
                blog += (dp * sp) * (da * sa);
            }
        }
        // final v: scale and store 8 floats (z = o*8..o*8+7)
        {
            float scl = posl ? sp : sa;
            int pix16 = pyr*4 + px;
            float4* dst = reinterpret_cast<float4*>(&s_out[pix16*OPIX + T*OT + o*8]);
            dst[0] = make_float4(pl[0]*scl, pl[1]*scl, pl[2]*scl, pl[3]*scl);
            dst[1] = make_float4(pl[4]*scl, pl[5]*scl, pl[6]*scl, pl[7]*scl);
        }
    }
    __syncthreads();

    // ---- output write: out[n][t][z][h][w] (16B runs of w) ----
    #pragma unroll
    for (int k = 0; k < 16; k++) {
        int e = tid + k*NTHR;           // 16 pixels x 256 (t,z)
        int pix = e & 15, tz = e >> 4;
        int t = tz >> 5, z = tz & 31;
        int gh = h0 + (pix >> 2), gw = w0 + (pix & 3);
        out[(((n*8 + t)*32 + z)*HW + gh)*HW + gw] = s_out[pix*OPIX + t*OT + z];
    }
}

extern "C" void kernel_launch(void* const* d_in, const int* in_sizes, int n_in,
                              void* d_out, int out_size)
{
    (void)in_sizes; (void)n_in; (void)out_size;
    const float* x  = (const float*)d_in[0];
    const float* Wc = (const float*)d_in[1];
    const float* Wp = (const float*)d_in[2];
    const float* Wa = (const float*)d_in[3];
    const float* Ba = (const float*)d_in[4];
    float* out = (float*)d_out;

    dim3 gA(3, 96, 16), bA(32, 8);
    k_transpose<<<gA, bA>>>(x);

    dim3 gB(HW/TW, HW/TH, NB);          // (24, 24, 4)
    k_caps<<<gB, NTHR>>>(Wc, Wp, Wa, Ba, out);
}